// round 15
// baseline (speedup 1.0000x reference)
#include <cuda_runtime.h>
#include <math.h>

// Problem constants (fixed by the dataset)
#define N_NODES   8192
#define N_EDGES   262144
#define BS_NODES  4096
#define N_SEND    2048
#define N_NOTS    (N_NODES - N_SEND)    // 6144
#define ZSTRIDE   18                    // 2 * (K+1)

// Unit pool layout (grab order = listed order)
#define U_PREP    8                     // build g_notS, 1024 nodes each
#define B_PRIOR   (U_PREP)              // 1 prior unit
#define B_FLT     (B_PRIOR + 1)         // 9
#define U_FLT     64                    // 4096 edges each
#define B_B       (B_FLT + U_FLT)       // 73
#define U_B       288                   // 8 seg * 36 triangle tile-pairs (256x256)
#define B_A       (B_B + U_B)           // 361
#define U_A       3072                  // 8 seg * 24 j-tiles * 16 i-chunks (256x128)
#define U_ALL     (B_A + U_A)           // 3433
#define GRID      1184                  // 8 blocks/SM x 148 SMs (64 warps/SM)

__device__ float g_part[U_ALL];         // one partial per unit
__device__ int   g_notS[N_NOTS];
__device__ unsigned int g_unit_ctr  = 0;
__device__ unsigned int g_prep_flag = 0;
__device__ unsigned int g_done_ctr  = 0;

// triangle tile-pair table: (a, b) with a <= b, 36 entries
__device__ const signed char TA[36] =
    {0,0,0,0,0,0,0,0, 1,1,1,1,1,1,1, 2,2,2,2,2,2, 3,3,3,3,3, 4,4,4,4, 5,5,5, 6,6, 7};
__device__ const signed char TB[36] =
    {0,1,2,3,4,5,6,7, 1,2,3,4,5,6,7, 2,3,4,5,6,7, 3,4,5,6,7, 4,5,6,7, 5,6,7, 6,7, 7};

// ---------------------------------------------------------------------------
// Packed fp32 (f32x2) helpers
// ---------------------------------------------------------------------------
typedef unsigned long long u64_t;
union F2U { float2 f; u64_t u; };

__device__ __forceinline__ u64_t f2u(float2 v) { F2U x; x.f = v; return x.u; }
__device__ __forceinline__ float2 u2f(u64_t v) { F2U x; x.u = v; return x.f; }

__device__ __forceinline__ float2 fma2(float2 a, float2 b, float2 c) {
    u64_t d;
    asm("fma.rn.f32x2 %0, %1, %2, %3;"
        : "=l"(d) : "l"(f2u(a)), "l"(f2u(b)), "l"(f2u(c)));
    return u2f(d);
}
__device__ __forceinline__ float2 mul2(float2 a, float2 b) {
    u64_t d;
    asm("mul.rn.f32x2 %0, %1, %2;" : "=l"(d) : "l"(f2u(a)), "l"(f2u(b)));
    return u2f(d);
}
__device__ __forceinline__ float2 add2(float2 a, float2 b) {
    u64_t d;
    asm("add.rn.f32x2 %0, %1, %2;" : "=l"(d) : "l"(f2u(a)), "l"(f2u(b)));
    return u2f(d);
}
__device__ __forceinline__ float2 neg2(float2 a) {
    F2U x; x.f = a; x.u ^= 0x8000000080000000ULL; return x.f;
}
__device__ __forceinline__ float2 abs2(float2 a) {
    F2U x; x.f = a; x.u &= 0x7FFFFFFF7FFFFFFFULL; return x.f;
}
__device__ __forceinline__ float2 sub2(float2 a, float2 b) { return add2(a, neg2(b)); }
__device__ __forceinline__ float2 splat2(float v) { return make_float2(v, v); }
#define FZERO splat2(0.0f)

__device__ __forceinline__ float fast_rsqrt(float x) {
    float r; asm("rsqrt.approx.f32 %0, %1;" : "=f"(r) : "f"(x)); return r;
}
__device__ __forceinline__ float fast_ex2(float x) {
    float r; asm("ex2.approx.f32 %0, %1;" : "=f"(r) : "f"(x)); return r;
}

// log2(erfc(t)) + ea for t >= 0 (njuffa-derived deg-5, log2(e) folded;
// |erf err| <= ~1.3e-4 worst case), final op fused with +ea.
__device__ __forceinline__ float2 log2_erfc_ea(float2 t, float2 ea) {
    const float2 D5 = splat2(-5.603370e-3f);
    const float2 D4 = splat2( 3.499207e-2f);
    const float2 D3 = splat2(-1.540479e-1f);
    const float2 D2 = splat2(-9.158902e-1f);
    const float2 D1 = splat2(-1.6283940f);
    float2 q = fma2(D5, t, D4);
    q = fma2(q, t, D3);
    q = fma2(q, t, D2);
    q = fma2(q, t, D1);
    return fma2(q, t, ea);
}

// Shared integral inner loop over ITERS f32x2 sender pairs.
// Math identical to the R10-verified chain: w = Zs0-Zr0, v = DZs-DZr,
// D=|w|^2, S=|v|^2(+1e-20 seed), C=-(v.w); diagonal flows to exactly 0;
// erf via ex - exp2(ea + log2_erfc(|x|)), sign restored by packed OR.
template <int ITERS>
__device__ __forceinline__ float2 integral_body(
    const float* sP, const float* sQ,
    float2 R0, float2 R1, float2 DR0, float2 DR1)
{
    const float2 L2E  = splat2(1.4426950408889634f);
    const float2 TINY = splat2(1e-20f);
    const u64_t  SGN  = 0x8000000080000000ULL;

    float2 acc = FZERO;
    #pragma unroll 4
    for (int i = 0; i < ITERS; i++) {
        const float4 P = *(const float4*)&sP[4 * i];
        const float4 Q = *(const float4*)&sQ[4 * i];
        const float2 A0  = make_float2(P.x, P.y);
        const float2 A1  = make_float2(P.z, P.w);
        const float2 Dz0 = make_float2(Q.x, Q.y);
        const float2 Dz1 = make_float2(Q.z, Q.w);

        const float2 w0 = sub2(A0, R0);
        const float2 w1 = sub2(A1, R1);
        const float2 v0 = sub2(Dz0, DR0);
        const float2 v1 = sub2(Dz1, DR1);

        const float2 Dv = fma2(w1, w1, mul2(w0, w0));
        const float2 Sv = fma2(v1, v1, fma2(v0, v0, TINY));
        const float2 nC = fma2(v1, w1, mul2(v0, w0));

        float2 irs;
        irs.x = fast_rsqrt(Sv.x);
        irs.y = fast_rsqrt(Sv.y);

        const float2 ncir = mul2(nC, irs);           // -mu*sqrt(S)
        const float2 x1   = fma2(Sv, irs, ncir);     // (1-mu)*sqrt(S)

        const float2 er = fma2(ncir, ncir, neg2(Dv));
        const float2 ea = mul2(er, L2E);

        const float2 q1 = log2_erfc_ea(abs2(x1),   ea);
        const float2 q2 = log2_erfc_ea(abs2(ncir), ea);

        float2 ex, G1, G2;
        ex.x = fast_ex2(ea.x);  ex.y = fast_ex2(ea.y);
        G1.x = fast_ex2(q1.x);  G1.y = fast_ex2(q1.y);
        G2.x = fast_ex2(q2.x);  G2.y = fast_ex2(q2.y);

        const float2 t1 = sub2(ex, G1);
        const float2 t2 = sub2(ex, G2);
        const float2 u1 = u2f(f2u(t1) | (f2u(x1)   & SGN));
        const float2 v2 = u2f(f2u(t2) | (f2u(ncir) & SGN));

        const float2 es = sub2(u1, v2);
        acc = fma2(es, irs, acc);
    }
    return acc;
}

// Block-level reduction of a per-thread scalar into ONE deterministic value
// (warp shfl + 8-element fixed-order sum by tid 0), stored to g_part[u].
__device__ __forceinline__ void unit_reduce_store(
    float val, int u, int wid, int lane, float* sRed)
{
    #pragma unroll
    for (int off = 16; off > 0; off >>= 1)
        val += __shfl_down_sync(0xFFFFFFFFu, val, off);
    if (lane == 0) sRed[wid] = val;
    __syncthreads();
    if (threadIdx.x == 0) {
        float s = 0.0f;
        #pragma unroll
        for (int w = 0; w < 8; w++) s += sRed[w];
        g_part[u] = s;
    }
}

// ---------------------------------------------------------------------------
// Fused kernel (single launch): one dynamic work-stealing pool:
//   [0, 8):      prep units (rank-compaction of non-senders; flag when done)
//   8:           prior unit
//   [9, 73):     flt units (memory-latency bound, early to overlap compute)
//   [73, 361):   B integral units: S x S triangle, 256x256 tiles, off-diag
//                x2 (f(i,j)==f(j,i) bit-exactly)
//   [361, 3433): A integral units: S-chunk(128) x notS-tile(256); A units
//                spin on the prep flag before reading g_notS (all GRID
//                blocks co-resident at 8/SM -> prep always completes).
// One partial per unit (bit-identical regardless of executing block).
// The LAST block to finish (threadfence-reduction pattern) does the
// fixed-order final combine, writes out[0], and resets the counters.
// ---------------------------------------------------------------------------
__global__ void __launch_bounds__(256, 8)
fused_kernel(const float* __restrict__ Z,
             const int*   __restrict__ su,
             const float* __restrict__ cp,
             const float* __restrict__ ts,
             const int*   __restrict__ snd,
             const int*   __restrict__ rcv,
             const int*   __restrict__ nodes,
             const float* __restrict__ beta_p,
             float*       __restrict__ out)
{
    __shared__ __align__(16) float sP[512], sQ[512];
    __shared__ float sRed[8];
    __shared__ int s_unit;
    __shared__ unsigned int s_rank;

    const int tid  = threadIdx.x;
    const int wid  = tid >> 5;
    const int lane = tid & 31;

    for (;;) {
        if (tid == 0) s_unit = (int)atomicAdd(&g_unit_ctr, 1u);
        __syncthreads();            // publishes s_unit; also: all threads are
                                    // past last unit's reads of sP/sQ/sRed
        const int u = s_unit;
        if (u >= U_ALL) break;

        if (u >= B_A) {
            // ---------------- A unit: S(128) x notS(256) ----------------
            const int ui  = u - B_A;
            const int k   = ui / 384;          // 0..7
            const int rem = ui % 384;
            const int jt  = rem >> 4;          // 0..23
            const int ic  = rem & 15;          // 0..15

            // wait for prep (first A grabs may race the prep units)
            if (tid == 0) {
                while (atomicAdd(&g_prep_flag, 0u) < U_PREP) {}
            }
            __syncthreads();

            const int jnode = g_notS[jt * 256 + tid];
            const float* zr = Z + jnode * ZSTRIDE;
            const float r0  = zr[k];
            const float rn0 = zr[k + 1];
            const float r1  = zr[9 + k];
            const float rn1 = zr[9 + k + 1];
            const float2 R0  = splat2(r0);
            const float2 R1  = splat2(r1);
            const float2 DR0 = splat2(rn0 - r0);
            const float2 DR1 = splat2(rn1 - r1);

            if (tid < 128) {
                const int sidx = su[ic * 128 + tid];
                const float* zs = Z + sidx * ZSTRIDE;
                const float a0 = zs[k];
                const float b0 = zs[k + 1];
                const float a1 = zs[9 + k];
                const float b1 = zs[9 + k + 1];
                const int base = 4 * (tid >> 1) + (tid & 1);
                sP[base]     = a0;
                sP[base + 2] = a1;
                sQ[base]     = b0 - a0;
                sQ[base + 2] = b1 - a1;
            }
            __syncthreads();

            const float2 acc = integral_body<64>(sP, sQ, R0, R1, DR0, DR1);

            const float dt = cp[k + 1] - cp[k];
            const float tot = (acc.x + acc.y) * (dt * 0.17677669529663687f);
            unit_reduce_store(tot, u, wid, lane, sRed);

        } else if (u >= B_B) {
            // ---------------- B unit: S x S triangle tile (256x256) -------
            const int ub = u - B_B;
            const int k  = ub / 36;
            const int tp = ub % 36;
            const int a = TA[tp], b = TB[tp];
            const float factor = (a == b) ? 1.0f : 2.0f;

            const int jnode = su[b * 256 + tid];
            const float* zr = Z + jnode * ZSTRIDE;
            const float r0  = zr[k];
            const float rn0 = zr[k + 1];
            const float r1  = zr[9 + k];
            const float rn1 = zr[9 + k + 1];
            const float2 R0  = splat2(r0);
            const float2 R1  = splat2(r1);
            const float2 DR0 = splat2(rn0 - r0);
            const float2 DR1 = splat2(rn1 - r1);

            {
                const int sidx = su[a * 256 + tid];
                const float* zs = Z + sidx * ZSTRIDE;
                const float a0 = zs[k];
                const float b0 = zs[k + 1];
                const float a1 = zs[9 + k];
                const float b1 = zs[9 + k + 1];
                const int base = 4 * (tid >> 1) + (tid & 1);
                sP[base]     = a0;
                sP[base + 2] = a1;
                sQ[base]     = b0 - a0;
                sQ[base + 2] = b1 - a1;
            }
            __syncthreads();

            const float2 acc = integral_body<128>(sP, sQ, R0, R1, DR0, DR1);

            const float dt = cp[k + 1] - cp[k];
            const float tot = (acc.x + acc.y) * (dt * factor * 0.17677669529663687f);
            unit_reduce_store(tot, u, wid, lane, sRed);

        } else if (u >= B_FLT) {
            // ---------------- flt unit (4096 edges) ----------------
            const int base = (u - B_FLT) * 4096;
            const float seg = cp[1] - cp[0];

            float acc = 0.0f;
            #pragma unroll 4
            for (int r = 0; r < 16; r++) {
                const int e = base + r * 256 + tid;
                const float t  = ts[e];
                const float q  = t / seg;
                const float kf = floorf(q);
                const int   ka = (int)kf;
                const float d  = q - kf;
                const float od = 1.0f - d;

                const float* zs = Z + snd[e] * ZSTRIDE;
                const float* zr = Z + rcv[e] * ZSTRIDE;
                const float sc0 = zs[ka],     sn0 = zs[ka + 1];
                const float sc1 = zs[9 + ka], sn1 = zs[9 + ka + 1];
                const float rc0 = zr[ka],     rn0 = zr[ka + 1];
                const float rc1 = zr[9 + ka], rn1 = zr[9 + ka + 1];

                const float scrc = sc0 * rc0 + sc1 * rc1;
                const float scsc = sc0 * sc0 + sc1 * sc1;
                const float rcrc = rc0 * rc0 + rc1 * rc1;
                const float scrn = sc0 * rn0 + sc1 * rn1;
                const float snrc = sn0 * rc0 + sn1 * rc1;
                const float scsn = sc0 * sn0 + sc1 * sn1;
                const float rcrn = rc0 * rn0 + rc1 * rn1;
                const float snrn = sn0 * rn0 + sn1 * rn1;
                const float snsn = sn0 * sn0 + sn1 * sn1;
                const float rnrn = rn0 * rn0 + rn1 * rn1;

                acc += od * od * (2.0f * scrc - scsc - rcrc)
                     + 2.0f * d * od * (scrn + snrc - scsn - rcrn)
                     + d * d * (2.0f * snrn - snsn - rnrn);
            }
            unit_reduce_store(acc, u, wid, lane, sRed);

        } else if (u == B_PRIOR) {
            // ---------------- prior unit (4096 nodes) ----------------
            float acc = 0.0f;
            #pragma unroll
            for (int r = 0; r < 16; r++) {
                const int n = nodes[r * 256 + tid];
                const float* z = Z + n * ZSTRIDE;
                #pragma unroll
                for (int dim = 0; dim < 2; dim++) {
                    const float* zd = z + dim * 9;
                    float prev = zd[0];
                    acc += prev * prev;
                    #pragma unroll
                    for (int kk = 1; kk <= 8; kk++) {
                        const float cur = zd[kk];
                        const float df  = cur - prev;
                        acc += df * df;
                        prev = cur;
                    }
                }
            }
            unit_reduce_store(acc, u, wid, lane, sRed);

        } else {
            // ---------------- prep unit: compact non-senders ----------------
            // rank(n) = #(su <= n) by binary search; if n not in su:
            // g_notS[n - rank] = n. Order-independent -> deterministic.
            #pragma unroll
            for (int r = 0; r < 4; r++) {
                const int n = u * 1024 + r * 256 + tid;
                int lo = 0, hi = N_SEND;
                while (lo < hi) {
                    const int mid = (lo + hi) >> 1;
                    if (su[mid] <= n) lo = mid + 1; else hi = mid;
                }
                const bool member = (lo > 0) && (su[lo - 1] == n);
                if (!member) g_notS[n - lo] = n;
            }
            __threadfence();
            __syncthreads();
            if (tid == 0) atomicAdd(&g_prep_flag, 1u);
        }
    }

    // ---------------- last-block final combine ----------------
    __threadfence();                       // make this block's g_part visible
    if (tid == 0) {
        const unsigned int prev = atomicAdd(&g_done_ctr, 1u);
        s_rank = prev;
    }
    __syncthreads();
    if (s_rank != GRID - 1) return;

    // This is the last block; all g_part writes are visible (fence+atomic).
    __shared__ float red[256];
    __shared__ float s_int, s_flt;

    float s = 0.0f;
    for (int i = B_B + tid; i < U_ALL; i += 256) s += g_part[i];
    red[tid] = s;
    __syncthreads();
    for (int st = 128; st > 0; st >>= 1) {
        if (tid < st) red[tid] += red[tid + st];
        __syncthreads();
    }
    if (tid == 0) s_int = red[0];
    __syncthreads();

    s = 0.0f;
    if (tid < U_FLT) s = g_part[B_FLT + tid];
    red[tid] = s;
    __syncthreads();
    for (int st = 128; st > 0; st >>= 1) {
        if (tid < st) red[tid] += red[tid + st];
        __syncthreads();
    }
    if (tid == 0) s_flt = red[0];
    __syncthreads();

    if (tid == 0) {
        const float beta   = beta_p[0];
        const float prior  = 10.0f * g_part[B_PRIOR];        // PENALTY
        const float result = 2.0f * (prior - beta * 262144.0f - s_flt
                              + 2.5066282746310002f * expf(beta) * s_int);
        out[0] = result;
        g_unit_ctr  = 0;   // reset for the next graph replay
        g_prep_flag = 0;
        g_done_ctr  = 0;
    }
}

// ---------------------------------------------------------------------------
extern "C" void kernel_launch(void* const* d_in, const int* in_sizes, int n_in,
                              void* d_out, int out_size)
{
    const float* Z    = (const float*)d_in[0];
    const float* beta = (const float*)d_in[1];
    const float* ts   = (const float*)d_in[2];
    const int*   snd  = (const int*)d_in[3];
    const int*   rcv  = (const int*)d_in[4];
    const int*   nds  = (const int*)d_in[5];
    const int*   su   = (const int*)d_in[6];
    const float* cp   = (const float*)d_in[7];
    float* out = (float*)d_out;

    fused_kernel<<<GRID, 256>>>(Z, su, cp, ts, snd, rcv, nds, beta, out);
}

// round 16
// speedup vs baseline: 1.0531x; 1.0531x over previous
#include <cuda_runtime.h>
#include <math.h>

// Problem constants (fixed by the dataset)
#define N_NODES   8192
#define N_EDGES   262144
#define BS_NODES  4096
#define N_SEND    2048
#define N_NOTS    (N_NODES - N_SEND)    // 6144
#define ZSTRIDE   18                    // 2 * (K+1)

// Unit pool layout (grab order = listed order)
#define U_PREP    8                     // build g_notS, 1024 nodes each
#define B_PRIOR   (U_PREP)              // 1 prior unit
#define B_FLT     (B_PRIOR + 1)         // 9
#define U_FLT     64                    // 4096 edges each
#define B_B       (B_FLT + U_FLT)       // 73
#define U_B       288                   // 8 seg * 36 triangle tile-pairs (256x256)
#define B_A       (B_B + U_B)           // 361
#define U_A       3072                  // 8 seg * 24 j-tiles * 16 i-chunks (256x128)
#define U_ALL     (B_A + U_A)           // 3433
#define N_PARTS   (U_ALL * 8)           // one slot per (unit, warp)
#define GRID      592                   // 4 * 148 SMs (all co-resident)

__device__ float g_part[N_PARTS];
__device__ int   g_notS[N_NOTS];
__device__ unsigned int g_unit_ctr  = 0;
__device__ unsigned int g_prep_flag = 0;

// triangle tile-pair table: (a, b) with a <= b, 36 entries
__device__ const signed char TA[36] =
    {0,0,0,0,0,0,0,0, 1,1,1,1,1,1,1, 2,2,2,2,2,2, 3,3,3,3,3, 4,4,4,4, 5,5,5, 6,6, 7};
__device__ const signed char TB[36] =
    {0,1,2,3,4,5,6,7, 1,2,3,4,5,6,7, 2,3,4,5,6,7, 3,4,5,6,7, 4,5,6,7, 5,6,7, 6,7, 7};

// ---------------------------------------------------------------------------
// Packed fp32 (f32x2) helpers
// ---------------------------------------------------------------------------
typedef unsigned long long u64_t;
union F2U { float2 f; u64_t u; };

__device__ __forceinline__ u64_t f2u(float2 v) { F2U x; x.f = v; return x.u; }
__device__ __forceinline__ float2 u2f(u64_t v) { F2U x; x.u = v; return x.f; }

__device__ __forceinline__ float2 fma2(float2 a, float2 b, float2 c) {
    u64_t d;
    asm("fma.rn.f32x2 %0, %1, %2, %3;"
        : "=l"(d) : "l"(f2u(a)), "l"(f2u(b)), "l"(f2u(c)));
    return u2f(d);
}
__device__ __forceinline__ float2 mul2(float2 a, float2 b) {
    u64_t d;
    asm("mul.rn.f32x2 %0, %1, %2;" : "=l"(d) : "l"(f2u(a)), "l"(f2u(b)));
    return u2f(d);
}
__device__ __forceinline__ float2 add2(float2 a, float2 b) {
    u64_t d;
    asm("add.rn.f32x2 %0, %1, %2;" : "=l"(d) : "l"(f2u(a)), "l"(f2u(b)));
    return u2f(d);
}
__device__ __forceinline__ float2 neg2(float2 a) {
    F2U x; x.f = a; x.u ^= 0x8000000080000000ULL; return x.f;
}
__device__ __forceinline__ float2 abs2(float2 a) {
    F2U x; x.f = a; x.u &= 0x7FFFFFFF7FFFFFFFULL; return x.f;
}
__device__ __forceinline__ float2 sub2(float2 a, float2 b) { return add2(a, neg2(b)); }
__device__ __forceinline__ float2 splat2(float v) { return make_float2(v, v); }
#define FZERO splat2(0.0f)

__device__ __forceinline__ float fast_rsqrt(float x) {
    float r; asm("rsqrt.approx.f32 %0, %1;" : "=f"(r) : "f"(x)); return r;
}
__device__ __forceinline__ float fast_ex2(float x) {
    float r; asm("ex2.approx.f32 %0, %1;" : "=f"(r) : "f"(x)); return r;
}

// log2(erfc(t)) + ea for t >= 0 (njuffa-derived deg-5, log2(e) folded;
// |erf err| <= ~1.3e-4 worst case), final op fused with +ea.
__device__ __forceinline__ float2 log2_erfc_ea(float2 t, float2 ea) {
    const float2 D5 = splat2(-5.603370e-3f);
    const float2 D4 = splat2( 3.499207e-2f);
    const float2 D3 = splat2(-1.540479e-1f);
    const float2 D2 = splat2(-9.158902e-1f);
    const float2 D1 = splat2(-1.6283940f);
    float2 q = fma2(D5, t, D4);
    q = fma2(q, t, D3);
    q = fma2(q, t, D2);
    q = fma2(q, t, D1);
    return fma2(q, t, ea);
}

// Shared integral inner loop over ITERS f32x2 sender pairs.
// Math identical to the R10-verified chain: w = Zs0-Zr0, v = DZs-DZr,
// D=|w|^2, S=|v|^2(+1e-20 seed), C=-(v.w); diagonal flows to exactly 0
// (uu=+0, nDl=-0 -> ea=+0 -> all exp2 == 1 -> terms == 0);
// erf via ex - exp2(ea + log2_erfc(|x|)), sign restored by packed OR.
// Unroll 8: doubles independent MUFU chains per warp (ex2/rsqrt lat 16).
template <int ITERS>
__device__ __forceinline__ float2 integral_body(
    const float* sP, const float* sQ,
    float2 R0, float2 R1, float2 DR0, float2 DR1)
{
    const float2 L2E  = splat2( 1.4426950408889634f);
    const float2 NL2E = splat2(-1.4426950408889634f);
    const float2 TINY = splat2(1e-20f);
    const u64_t  SGN  = 0x8000000080000000ULL;

    float2 acc = FZERO;
    #pragma unroll 8
    for (int i = 0; i < ITERS; i++) {
        const float4 P = *(const float4*)&sP[4 * i];
        const float4 Q = *(const float4*)&sQ[4 * i];
        const float2 A0  = make_float2(P.x, P.y);
        const float2 A1  = make_float2(P.z, P.w);
        const float2 Dz0 = make_float2(Q.x, Q.y);
        const float2 Dz1 = make_float2(Q.z, Q.w);

        const float2 w0 = sub2(A0, R0);
        const float2 w1 = sub2(A1, R1);
        const float2 v0 = sub2(Dz0, DR0);
        const float2 v1 = sub2(Dz1, DR1);

        const float2 Dv = fma2(w1, w1, mul2(w0, w0));
        const float2 Sv = fma2(v1, v1, fma2(v0, v0, TINY));
        const float2 nC = fma2(v1, w1, mul2(v0, w0));

        float2 irs;
        irs.x = fast_rsqrt(Sv.x);
        irs.y = fast_rsqrt(Sv.y);

        const float2 ncir = mul2(nC, irs);           // -mu*sqrt(S)
        const float2 x1   = fma2(Sv, irs, ncir);     // (1-mu)*sqrt(S)

        // ea = (ncir^2 - D) * l2e, no negate needed
        const float2 uu  = mul2(ncir, ncir);
        const float2 nDl = mul2(Dv, NL2E);
        const float2 ea  = fma2(uu, L2E, nDl);

        const float2 q1 = log2_erfc_ea(abs2(x1),   ea);
        const float2 q2 = log2_erfc_ea(abs2(ncir), ea);

        float2 ex, G1, G2;
        ex.x = fast_ex2(ea.x);  ex.y = fast_ex2(ea.y);
        G1.x = fast_ex2(q1.x);  G1.y = fast_ex2(q1.y);
        G2.x = fast_ex2(q2.x);  G2.y = fast_ex2(q2.y);

        const float2 t1 = sub2(ex, G1);
        const float2 t2 = sub2(ex, G2);
        const float2 u1 = u2f(f2u(t1) | (f2u(x1)   & SGN));
        const float2 v2 = u2f(f2u(t2) | (f2u(ncir) & SGN));

        const float2 es = sub2(u1, v2);
        acc = fma2(es, irs, acc);
    }
    return acc;
}

// ---------------------------------------------------------------------------
// Fused kernel: one dynamic work-stealing pool:
//   [0, 8):      prep units (rank-compaction of non-senders; flag when done)
//   8:           prior unit
//   [9, 73):     flt units (memory-latency bound, early to overlap compute)
//   [73, 361):   B integral units: S x S triangle, 256x256 tiles, off-diag
//                x2 (f(i,j)==f(j,i) bit-exactly)
//   [361, 3433): A integral units: S-chunk(128) x notS-tile(256); A units
//                spin on the prep flag ONCE per block (register latch)
//                before reading g_notS (all GRID blocks co-resident).
// Per-(unit,warp) partial slots -> fixed-order final sum is deterministic.
// ---------------------------------------------------------------------------
__global__ void __launch_bounds__(256)
fused_kernel(const float* __restrict__ Z,
             const int*   __restrict__ su,
             const float* __restrict__ cp,
             const float* __restrict__ ts,
             const int*   __restrict__ snd,
             const int*   __restrict__ rcv,
             const int*   __restrict__ nodes)
{
    __shared__ __align__(16) float sP[512], sQ[512];
    __shared__ int s_unit[2];

    const int tid  = threadIdx.x;
    const int wid  = tid >> 5;
    const int lane = tid & 31;
    bool prep_ok = false;   // per-thread latch, branch is block-uniform

    for (int it = 0; ; it++) {
        const int p = it & 1;
        if (tid == 0) s_unit[p] = (int)atomicAdd(&g_unit_ctr, 1u);
        __syncthreads();            // publishes s_unit[p]; also guards sP/sQ
        const int u = s_unit[p];
        if (u >= U_ALL) break;

        if (u >= B_A) {
            // ---------------- A unit: S(128) x notS(256) ----------------
            const int ui  = u - B_A;
            const int k   = ui / 384;          // 0..7
            const int rem = ui % 384;
            const int jt  = rem >> 4;          // 0..23
            const int ic  = rem & 15;          // 0..15

            // wait for prep only once per block (uniform branch)
            if (!prep_ok) {
                if (tid == 0) {
                    while (atomicAdd(&g_prep_flag, 0u) < U_PREP) {}
                }
                __syncthreads();
                prep_ok = true;
            }

            const int jnode = g_notS[jt * 256 + tid];
            const float* zr = Z + jnode * ZSTRIDE;
            const float r0  = zr[k];
            const float rn0 = zr[k + 1];
            const float r1  = zr[9 + k];
            const float rn1 = zr[9 + k + 1];
            const float2 R0  = splat2(r0);
            const float2 R1  = splat2(r1);
            const float2 DR0 = splat2(rn0 - r0);
            const float2 DR1 = splat2(rn1 - r1);

            if (tid < 128) {
                const int sidx = su[ic * 128 + tid];
                const float* zs = Z + sidx * ZSTRIDE;
                const float a0 = zs[k];
                const float b0 = zs[k + 1];
                const float a1 = zs[9 + k];
                const float b1 = zs[9 + k + 1];
                const int base = 4 * (tid >> 1) + (tid & 1);
                sP[base]     = a0;
                sP[base + 2] = a1;
                sQ[base]     = b0 - a0;
                sQ[base + 2] = b1 - a1;
            }
            __syncthreads();

            const float2 acc = integral_body<64>(sP, sQ, R0, R1, DR0, DR1);

            const float dt = cp[k + 1] - cp[k];
            float tot = (acc.x + acc.y) * (dt * 0.17677669529663687f);
            #pragma unroll
            for (int off = 16; off > 0; off >>= 1)
                tot += __shfl_down_sync(0xFFFFFFFFu, tot, off);
            if (lane == 0) g_part[u * 8 + wid] = tot;

        } else if (u >= B_B) {
            // ---------------- B unit: S x S triangle tile (256x256) -------
            const int ub = u - B_B;
            const int k  = ub / 36;
            const int tp = ub % 36;
            const int a = TA[tp], b = TB[tp];
            const float factor = (a == b) ? 1.0f : 2.0f;

            const int jnode = su[b * 256 + tid];
            const float* zr = Z + jnode * ZSTRIDE;
            const float r0  = zr[k];
            const float rn0 = zr[k + 1];
            const float r1  = zr[9 + k];
            const float rn1 = zr[9 + k + 1];
            const float2 R0  = splat2(r0);
            const float2 R1  = splat2(r1);
            const float2 DR0 = splat2(rn0 - r0);
            const float2 DR1 = splat2(rn1 - r1);

            {
                const int sidx = su[a * 256 + tid];
                const float* zs = Z + sidx * ZSTRIDE;
                const float a0 = zs[k];
                const float b0 = zs[k + 1];
                const float a1 = zs[9 + k];
                const float b1 = zs[9 + k + 1];
                const int base = 4 * (tid >> 1) + (tid & 1);
                sP[base]     = a0;
                sP[base + 2] = a1;
                sQ[base]     = b0 - a0;
                sQ[base + 2] = b1 - a1;
            }
            __syncthreads();

            const float2 acc = integral_body<128>(sP, sQ, R0, R1, DR0, DR1);

            const float dt = cp[k + 1] - cp[k];
            float tot = (acc.x + acc.y) * (dt * factor * 0.17677669529663687f);
            #pragma unroll
            for (int off = 16; off > 0; off >>= 1)
                tot += __shfl_down_sync(0xFFFFFFFFu, tot, off);
            if (lane == 0) g_part[u * 8 + wid] = tot;

        } else if (u >= B_FLT) {
            // ---------------- flt unit (4096 edges) ----------------
            const int base = (u - B_FLT) * 4096;
            const float seg = cp[1] - cp[0];

            float acc = 0.0f;
            #pragma unroll 4
            for (int r = 0; r < 16; r++) {
                const int e = base + r * 256 + tid;
                const float t  = ts[e];
                const float q  = t / seg;
                const float kf = floorf(q);
                const int   ka = (int)kf;
                const float d  = q - kf;
                const float od = 1.0f - d;

                const float* zs = Z + snd[e] * ZSTRIDE;
                const float* zr = Z + rcv[e] * ZSTRIDE;
                const float sc0 = zs[ka],     sn0 = zs[ka + 1];
                const float sc1 = zs[9 + ka], sn1 = zs[9 + ka + 1];
                const float rc0 = zr[ka],     rn0 = zr[ka + 1];
                const float rc1 = zr[9 + ka], rn1 = zr[9 + ka + 1];

                const float scrc = sc0 * rc0 + sc1 * rc1;
                const float scsc = sc0 * sc0 + sc1 * sc1;
                const float rcrc = rc0 * rc0 + rc1 * rc1;
                const float scrn = sc0 * rn0 + sc1 * rn1;
                const float snrc = sn0 * rc0 + sn1 * rc1;
                const float scsn = sc0 * sn0 + sc1 * sn1;
                const float rcrn = rc0 * rn0 + rc1 * rn1;
                const float snrn = sn0 * rn0 + sn1 * rn1;
                const float snsn = sn0 * sn0 + sn1 * sn1;
                const float rnrn = rn0 * rn0 + rn1 * rn1;

                acc += od * od * (2.0f * scrc - scsc - rcrc)
                     + 2.0f * d * od * (scrn + snrc - scsn - rcrn)
                     + d * d * (2.0f * snrn - snsn - rnrn);
            }
            #pragma unroll
            for (int off = 16; off > 0; off >>= 1)
                acc += __shfl_down_sync(0xFFFFFFFFu, acc, off);
            if (lane == 0) g_part[u * 8 + wid] = acc;

        } else if (u == B_PRIOR) {
            // ---------------- prior unit (4096 nodes) ----------------
            float acc = 0.0f;
            #pragma unroll
            for (int r = 0; r < 16; r++) {
                const int n = nodes[r * 256 + tid];
                const float* z = Z + n * ZSTRIDE;
                #pragma unroll
                for (int dim = 0; dim < 2; dim++) {
                    const float* zd = z + dim * 9;
                    float prev = zd[0];
                    acc += prev * prev;
                    #pragma unroll
                    for (int kk = 1; kk <= 8; kk++) {
                        const float cur = zd[kk];
                        const float df  = cur - prev;
                        acc += df * df;
                        prev = cur;
                    }
                }
            }
            #pragma unroll
            for (int off = 16; off > 0; off >>= 1)
                acc += __shfl_down_sync(0xFFFFFFFFu, acc, off);
            if (lane == 0) g_part[u * 8 + wid] = acc;

        } else {
            // ---------------- prep unit: compact non-senders ----------------
            // rank(n) = #(su <= n) by binary search; if n not in su:
            // g_notS[n - rank] = n. Order-independent -> deterministic.
            #pragma unroll
            for (int r = 0; r < 4; r++) {
                const int n = u * 1024 + r * 256 + tid;
                int lo = 0, hi = N_SEND;
                while (lo < hi) {
                    const int mid = (lo + hi) >> 1;
                    if (su[mid] <= n) lo = mid + 1; else hi = mid;
                }
                const bool member = (lo > 0) && (su[lo - 1] == n);
                if (!member) g_notS[n - lo] = n;
            }
            __threadfence();
            __syncthreads();
            if (tid == 0) atomicAdd(&g_prep_flag, 1u);
        }
    }
}

// ---------------------------------------------------------------------------
// Final combine: fixed-order parallel reduction over the slot ranges,
// then scalar combine + counter/flag reset for graph replay.
// ---------------------------------------------------------------------------
__global__ void __launch_bounds__(512)
final_kernel(const float* __restrict__ beta_p, float* __restrict__ out)
{
    __shared__ float red[512];
    __shared__ float s_int, s_flt;
    const int tid = threadIdx.x;

    // integral slots [B_B*8, U_ALL*8)
    float s = 0.0f;
    for (int i = B_B * 8 + tid; i < U_ALL * 8; i += 512) s += g_part[i];
    red[tid] = s;
    __syncthreads();
    for (int st = 256; st > 0; st >>= 1) {
        if (tid < st) red[tid] += red[tid + st];
        __syncthreads();
    }
    if (tid == 0) s_int = red[0];
    __syncthreads();

    // flt slots [B_FLT*8, B_B*8) -- exactly 512
    red[tid] = g_part[B_FLT * 8 + tid];
    __syncthreads();
    for (int st = 256; st > 0; st >>= 1) {
        if (tid < st) red[tid] += red[tid + st];
        __syncthreads();
    }
    if (tid == 0) s_flt = red[0];
    __syncthreads();

    if (tid == 0) {
        float prior_raw = 0.0f;
        #pragma unroll
        for (int i = 0; i < 8; i++) prior_raw += g_part[B_PRIOR * 8 + i];

        const float beta   = beta_p[0];
        const float prior  = 10.0f * prior_raw;              // PENALTY
        const float result = 2.0f * (prior - beta * 262144.0f - s_flt
                              + 2.5066282746310002f * expf(beta) * s_int);
        out[0] = result;
        g_unit_ctr  = 0;   // reset for next graph replay
        g_prep_flag = 0;
    }
}

// ---------------------------------------------------------------------------
extern "C" void kernel_launch(void* const* d_in, const int* in_sizes, int n_in,
                              void* d_out, int out_size)
{
    const float* Z    = (const float*)d_in[0];
    const float* beta = (const float*)d_in[1];
    const float* ts   = (const float*)d_in[2];
    const int*   snd  = (const int*)d_in[3];
    const int*   rcv  = (const int*)d_in[4];
    const int*   nds  = (const int*)d_in[5];
    const int*   su   = (const int*)d_in[6];
    const float* cp   = (const float*)d_in[7];
    float* out = (float*)d_out;

    fused_kernel<<<GRID, 256>>>(Z, su, cp, ts, snd, rcv, nds);
    final_kernel<<<1, 512>>>(beta, out);
}

// round 17
// speedup vs baseline: 1.0706x; 1.0166x over previous
#include <cuda_runtime.h>
#include <math.h>

// Problem constants (fixed by the dataset)
#define N_NODES   8192
#define N_EDGES   262144
#define BS_NODES  4096
#define N_SEND    2048
#define N_NOTS    (N_NODES - N_SEND)    // 6144
#define ZSTRIDE   18                    // 2 * (K+1)

// Unit pool layout (grab order = listed order)
#define U_PREP    8                     // build g_notS, 1024 nodes each
#define B_PRIOR   (U_PREP)              // 1 prior unit
#define B_FLT     (B_PRIOR + 1)         // 9
#define U_FLT     64                    // 4096 edges each
#define B_B       (B_FLT + U_FLT)       // 73
#define U_B       288                   // 8 seg * 36 triangle tile-pairs (256x256)
#define B_A       (B_B + U_B)           // 361
#define U_A       3072                  // 8 seg * 24 j-tiles * 16 i-chunks (256x128)
#define U_ALL     (B_A + U_A)           // 3433
#define N_PARTS   (U_ALL * 8)           // one slot per (unit, warp)
#define GRID      592                   // 4 * 148 SMs (all co-resident)

__device__ float g_part[N_PARTS];
__device__ int   g_notS[N_NOTS];
__device__ unsigned int g_unit_ctr  = 0;
__device__ unsigned int g_prep_flag = 0;

// triangle tile-pair table: (a, b) with a <= b, 36 entries
__device__ const signed char TA[36] =
    {0,0,0,0,0,0,0,0, 1,1,1,1,1,1,1, 2,2,2,2,2,2, 3,3,3,3,3, 4,4,4,4, 5,5,5, 6,6, 7};
__device__ const signed char TB[36] =
    {0,1,2,3,4,5,6,7, 1,2,3,4,5,6,7, 2,3,4,5,6,7, 3,4,5,6,7, 4,5,6,7, 5,6,7, 6,7, 7};

// ---------------------------------------------------------------------------
// Packed fp32 (f32x2) helpers
// ---------------------------------------------------------------------------
typedef unsigned long long u64_t;
union F2U { float2 f; u64_t u; };

__device__ __forceinline__ u64_t f2u(float2 v) { F2U x; x.f = v; return x.u; }
__device__ __forceinline__ float2 u2f(u64_t v) { F2U x; x.u = v; return x.f; }

__device__ __forceinline__ float2 fma2(float2 a, float2 b, float2 c) {
    u64_t d;
    asm("fma.rn.f32x2 %0, %1, %2, %3;"
        : "=l"(d) : "l"(f2u(a)), "l"(f2u(b)), "l"(f2u(c)));
    return u2f(d);
}
__device__ __forceinline__ float2 mul2(float2 a, float2 b) {
    u64_t d;
    asm("mul.rn.f32x2 %0, %1, %2;" : "=l"(d) : "l"(f2u(a)), "l"(f2u(b)));
    return u2f(d);
}
__device__ __forceinline__ float2 add2(float2 a, float2 b) {
    u64_t d;
    asm("add.rn.f32x2 %0, %1, %2;" : "=l"(d) : "l"(f2u(a)), "l"(f2u(b)));
    return u2f(d);
}
__device__ __forceinline__ float2 neg2(float2 a) {
    F2U x; x.f = a; x.u ^= 0x8000000080000000ULL; return x.f;
}
__device__ __forceinline__ float2 abs2(float2 a) {
    F2U x; x.f = a; x.u &= 0x7FFFFFFF7FFFFFFFULL; return x.f;
}
__device__ __forceinline__ float2 sub2(float2 a, float2 b) { return add2(a, neg2(b)); }
__device__ __forceinline__ float2 splat2(float v) { return make_float2(v, v); }
#define FZERO splat2(0.0f)

__device__ __forceinline__ float fast_rsqrt(float x) {
    float r; asm("rsqrt.approx.f32 %0, %1;" : "=f"(r) : "f"(x)); return r;
}
__device__ __forceinline__ float fast_ex2(float x) {
    float r; asm("ex2.approx.f32 %0, %1;" : "=f"(r) : "f"(x)); return r;
}

// log2(erfc(t)) + ea for t >= 0 (njuffa-derived deg-5, log2(e) folded;
// |erf err| <= ~1.3e-4 worst case), final op fused with +ea.
__device__ __forceinline__ float2 log2_erfc_ea(float2 t, float2 ea) {
    const float2 D5 = splat2(-5.603370e-3f);
    const float2 D4 = splat2( 3.499207e-2f);
    const float2 D3 = splat2(-1.540479e-1f);
    const float2 D2 = splat2(-9.158902e-1f);
    const float2 D1 = splat2(-1.6283940f);
    float2 q = fma2(D5, t, D4);
    q = fma2(q, t, D3);
    q = fma2(q, t, D2);
    q = fma2(q, t, D1);
    return fma2(q, t, ea);
}

// Shared integral inner loop over ITERS f32x2 sender pairs.
// Math identical to the R10/R12-verified chain: w = Zs0-Zr0, v = DZs-DZr,
// D=|w|^2, S=|v|^2(+1e-20 seed), C=-(v.w); diagonal flows to exactly 0;
// erf via ex - exp2(ea + log2_erfc(|x|)), sign restored by packed OR.
template <int ITERS>
__device__ __forceinline__ float2 integral_body(
    const float* sP, const float* sQ,
    float2 R0, float2 R1, float2 DR0, float2 DR1)
{
    const float2 L2E  = splat2(1.4426950408889634f);
    const float2 TINY = splat2(1e-20f);
    const u64_t  SGN  = 0x8000000080000000ULL;

    float2 acc = FZERO;
    #pragma unroll 4
    for (int i = 0; i < ITERS; i++) {
        const float4 P = *(const float4*)&sP[4 * i];
        const float4 Q = *(const float4*)&sQ[4 * i];
        const float2 A0  = make_float2(P.x, P.y);
        const float2 A1  = make_float2(P.z, P.w);
        const float2 Dz0 = make_float2(Q.x, Q.y);
        const float2 Dz1 = make_float2(Q.z, Q.w);

        const float2 w0 = sub2(A0, R0);
        const float2 w1 = sub2(A1, R1);
        const float2 v0 = sub2(Dz0, DR0);
        const float2 v1 = sub2(Dz1, DR1);

        const float2 Dv = fma2(w1, w1, mul2(w0, w0));
        const float2 Sv = fma2(v1, v1, fma2(v0, v0, TINY));
        const float2 nC = fma2(v1, w1, mul2(v0, w0));

        float2 irs;
        irs.x = fast_rsqrt(Sv.x);
        irs.y = fast_rsqrt(Sv.y);

        const float2 ncir = mul2(nC, irs);           // -mu*sqrt(S)
        const float2 x1   = fma2(Sv, irs, ncir);     // (1-mu)*sqrt(S)

        const float2 er = fma2(ncir, ncir, neg2(Dv));
        const float2 ea = mul2(er, L2E);

        const float2 q1 = log2_erfc_ea(abs2(x1),   ea);
        const float2 q2 = log2_erfc_ea(abs2(ncir), ea);

        float2 ex, G1, G2;
        ex.x = fast_ex2(ea.x);  ex.y = fast_ex2(ea.y);
        G1.x = fast_ex2(q1.x);  G1.y = fast_ex2(q1.y);
        G2.x = fast_ex2(q2.x);  G2.y = fast_ex2(q2.y);

        const float2 t1 = sub2(ex, G1);
        const float2 t2 = sub2(ex, G2);
        const float2 u1 = u2f(f2u(t1) | (f2u(x1)   & SGN));
        const float2 v2 = u2f(f2u(t2) | (f2u(ncir) & SGN));

        const float2 es = sub2(u1, v2);
        acc = fma2(es, irs, acc);
    }
    return acc;
}

// ---------------------------------------------------------------------------
// Fused kernel: one dynamic work-stealing pool:
//   [0, 8):      prep units (rank-compaction of non-senders; flag when done)
//   8:           prior unit
//   [9, 73):     flt units (memory-latency bound, early to overlap compute)
//   [73, 361):   B integral units: S x S triangle, 256x256 tiles, off-diag
//                x2 (f(i,j)==f(j,i) bit-exactly)
//   [361, 3433): A integral units: S-chunk(128) x notS-tile(256); A units
//                spin on the prep flag ONCE per block (register latch,
//                block-uniform branch) before reading g_notS (all GRID
//                blocks co-resident -> prep always completes).
// Per-(unit,warp) partial slots -> fixed-order final sum is deterministic.
// ---------------------------------------------------------------------------
__global__ void __launch_bounds__(256)
fused_kernel(const float* __restrict__ Z,
             const int*   __restrict__ su,
             const float* __restrict__ cp,
             const float* __restrict__ ts,
             const int*   __restrict__ snd,
             const int*   __restrict__ rcv,
             const int*   __restrict__ nodes)
{
    __shared__ __align__(16) float sP[512], sQ[512];
    __shared__ int s_unit[2];

    const int tid  = threadIdx.x;
    const int wid  = tid >> 5;
    const int lane = tid & 31;
    bool prep_ok = false;   // per-thread latch, branch is block-uniform

    for (int it = 0; ; it++) {
        const int p = it & 1;
        if (tid == 0) s_unit[p] = (int)atomicAdd(&g_unit_ctr, 1u);
        __syncthreads();            // publishes s_unit[p]; also guards sP/sQ
        const int u = s_unit[p];
        if (u >= U_ALL) break;

        if (u >= B_A) {
            // ---------------- A unit: S(128) x notS(256) ----------------
            const int ui  = u - B_A;
            const int k   = ui / 384;          // 0..7
            const int rem = ui % 384;
            const int jt  = rem >> 4;          // 0..23
            const int ic  = rem & 15;          // 0..15

            // wait for prep only once per block (uniform branch)
            if (!prep_ok) {
                if (tid == 0) {
                    while (atomicAdd(&g_prep_flag, 0u) < U_PREP) {}
                }
                __syncthreads();
                prep_ok = true;
            }

            const int jnode = g_notS[jt * 256 + tid];
            const float* zr = Z + jnode * ZSTRIDE;
            const float r0  = zr[k];
            const float rn0 = zr[k + 1];
            const float r1  = zr[9 + k];
            const float rn1 = zr[9 + k + 1];
            const float2 R0  = splat2(r0);
            const float2 R1  = splat2(r1);
            const float2 DR0 = splat2(rn0 - r0);
            const float2 DR1 = splat2(rn1 - r1);

            if (tid < 128) {
                const int sidx = su[ic * 128 + tid];
                const float* zs = Z + sidx * ZSTRIDE;
                const float a0 = zs[k];
                const float b0 = zs[k + 1];
                const float a1 = zs[9 + k];
                const float b1 = zs[9 + k + 1];
                const int base = 4 * (tid >> 1) + (tid & 1);
                sP[base]     = a0;
                sP[base + 2] = a1;
                sQ[base]     = b0 - a0;
                sQ[base + 2] = b1 - a1;
            }
            __syncthreads();

            const float2 acc = integral_body<64>(sP, sQ, R0, R1, DR0, DR1);

            const float dt = cp[k + 1] - cp[k];
            float tot = (acc.x + acc.y) * (dt * 0.17677669529663687f);
            #pragma unroll
            for (int off = 16; off > 0; off >>= 1)
                tot += __shfl_down_sync(0xFFFFFFFFu, tot, off);
            if (lane == 0) g_part[u * 8 + wid] = tot;

        } else if (u >= B_B) {
            // ---------------- B unit: S x S triangle tile (256x256) -------
            const int ub = u - B_B;
            const int k  = ub / 36;
            const int tp = ub % 36;
            const int a = TA[tp], b = TB[tp];
            const float factor = (a == b) ? 1.0f : 2.0f;

            const int jnode = su[b * 256 + tid];
            const float* zr = Z + jnode * ZSTRIDE;
            const float r0  = zr[k];
            const float rn0 = zr[k + 1];
            const float r1  = zr[9 + k];
            const float rn1 = zr[9 + k + 1];
            const float2 R0  = splat2(r0);
            const float2 R1  = splat2(r1);
            const float2 DR0 = splat2(rn0 - r0);
            const float2 DR1 = splat2(rn1 - r1);

            {
                const int sidx = su[a * 256 + tid];
                const float* zs = Z + sidx * ZSTRIDE;
                const float a0 = zs[k];
                const float b0 = zs[k + 1];
                const float a1 = zs[9 + k];
                const float b1 = zs[9 + k + 1];
                const int base = 4 * (tid >> 1) + (tid & 1);
                sP[base]     = a0;
                sP[base + 2] = a1;
                sQ[base]     = b0 - a0;
                sQ[base + 2] = b1 - a1;
            }
            __syncthreads();

            const float2 acc = integral_body<128>(sP, sQ, R0, R1, DR0, DR1);

            const float dt = cp[k + 1] - cp[k];
            float tot = (acc.x + acc.y) * (dt * factor * 0.17677669529663687f);
            #pragma unroll
            for (int off = 16; off > 0; off >>= 1)
                tot += __shfl_down_sync(0xFFFFFFFFu, tot, off);
            if (lane == 0) g_part[u * 8 + wid] = tot;

        } else if (u >= B_FLT) {
            // ---------------- flt unit (4096 edges) ----------------
            const int base = (u - B_FLT) * 4096;
            const float seg = cp[1] - cp[0];

            float acc = 0.0f;
            #pragma unroll 4
            for (int r = 0; r < 16; r++) {
                const int e = base + r * 256 + tid;
                const float t  = ts[e];
                const float q  = t / seg;
                const float kf = floorf(q);
                const int   ka = (int)kf;
                const float d  = q - kf;
                const float od = 1.0f - d;

                const float* zs = Z + snd[e] * ZSTRIDE;
                const float* zr = Z + rcv[e] * ZSTRIDE;
                const float sc0 = zs[ka],     sn0 = zs[ka + 1];
                const float sc1 = zs[9 + ka], sn1 = zs[9 + ka + 1];
                const float rc0 = zr[ka],     rn0 = zr[ka + 1];
                const float rc1 = zr[9 + ka], rn1 = zr[9 + ka + 1];

                const float scrc = sc0 * rc0 + sc1 * rc1;
                const float scsc = sc0 * sc0 + sc1 * sc1;
                const float rcrc = rc0 * rc0 + rc1 * rc1;
                const float scrn = sc0 * rn0 + sc1 * rn1;
                const float snrc = sn0 * rc0 + sn1 * rc1;
                const float scsn = sc0 * sn0 + sc1 * sn1;
                const float rcrn = rc0 * rn0 + rc1 * rn1;
                const float snrn = sn0 * rn0 + sn1 * rn1;
                const float snsn = sn0 * sn0 + sn1 * sn1;
                const float rnrn = rn0 * rn0 + rn1 * rn1;

                acc += od * od * (2.0f * scrc - scsc - rcrc)
                     + 2.0f * d * od * (scrn + snrc - scsn - rcrn)
                     + d * d * (2.0f * snrn - snsn - rnrn);
            }
            #pragma unroll
            for (int off = 16; off > 0; off >>= 1)
                acc += __shfl_down_sync(0xFFFFFFFFu, acc, off);
            if (lane == 0) g_part[u * 8 + wid] = acc;

        } else if (u == B_PRIOR) {
            // ---------------- prior unit (4096 nodes) ----------------
            float acc = 0.0f;
            #pragma unroll
            for (int r = 0; r < 16; r++) {
                const int n = nodes[r * 256 + tid];
                const float* z = Z + n * ZSTRIDE;
                #pragma unroll
                for (int dim = 0; dim < 2; dim++) {
                    const float* zd = z + dim * 9;
                    float prev = zd[0];
                    acc += prev * prev;
                    #pragma unroll
                    for (int kk = 1; kk <= 8; kk++) {
                        const float cur = zd[kk];
                        const float df  = cur - prev;
                        acc += df * df;
                        prev = cur;
                    }
                }
            }
            #pragma unroll
            for (int off = 16; off > 0; off >>= 1)
                acc += __shfl_down_sync(0xFFFFFFFFu, acc, off);
            if (lane == 0) g_part[u * 8 + wid] = acc;

        } else {
            // ---------------- prep unit: compact non-senders ----------------
            // rank(n) = #(su <= n) by binary search; if n not in su:
            // g_notS[n - rank] = n. Order-independent -> deterministic.
            #pragma unroll
            for (int r = 0; r < 4; r++) {
                const int n = u * 1024 + r * 256 + tid;
                int lo = 0, hi = N_SEND;
                while (lo < hi) {
                    const int mid = (lo + hi) >> 1;
                    if (su[mid] <= n) lo = mid + 1; else hi = mid;
                }
                const bool member = (lo > 0) && (su[lo - 1] == n);
                if (!member) g_notS[n - lo] = n;
            }
            __threadfence();
            __syncthreads();
            if (tid == 0) atomicAdd(&g_prep_flag, 1u);
        }
    }
}

// ---------------------------------------------------------------------------
// Final combine: fixed-order parallel reduction over the slot ranges,
// then scalar combine + counter/flag reset for graph replay.
// ---------------------------------------------------------------------------
__global__ void __launch_bounds__(512)
final_kernel(const float* __restrict__ beta_p, float* __restrict__ out)
{
    __shared__ float red[512];
    __shared__ float s_int, s_flt;
    const int tid = threadIdx.x;

    // integral slots [B_B*8, U_ALL*8)
    float s = 0.0f;
    for (int i = B_B * 8 + tid; i < U_ALL * 8; i += 512) s += g_part[i];
    red[tid] = s;
    __syncthreads();
    for (int st = 256; st > 0; st >>= 1) {
        if (tid < st) red[tid] += red[tid + st];
        __syncthreads();
    }
    if (tid == 0) s_int = red[0];
    __syncthreads();

    // flt slots [B_FLT*8, B_B*8) -- exactly 512
    red[tid] = g_part[B_FLT * 8 + tid];
    __syncthreads();
    for (int st = 256; st > 0; st >>= 1) {
        if (tid < st) red[tid] += red[tid + st];
        __syncthreads();
    }
    if (tid == 0) s_flt = red[0];
    __syncthreads();

    if (tid == 0) {
        float prior_raw = 0.0f;
        #pragma unroll
        for (int i = 0; i < 8; i++) prior_raw += g_part[B_PRIOR * 8 + i];

        const float beta   = beta_p[0];
        const float prior  = 10.0f * prior_raw;              // PENALTY
        const float result = 2.0f * (prior - beta * 262144.0f - s_flt
                              + 2.5066282746310002f * expf(beta) * s_int);
        out[0] = result;
        g_unit_ctr  = 0;   // reset for next graph replay
        g_prep_flag = 0;
    }
}

// ---------------------------------------------------------------------------
extern "C" void kernel_launch(void* const* d_in, const int* in_sizes, int n_in,
                              void* d_out, int out_size)
{
    const float* Z    = (const float*)d_in[0];
    const float* beta = (const float*)d_in[1];
    const float* ts   = (const float*)d_in[2];
    const int*   snd  = (const int*)d_in[3];
    const int*   rcv  = (const int*)d_in[4];
    const int*   nds  = (const int*)d_in[5];
    const int*   su   = (const int*)d_in[6];
    const float* cp   = (const float*)d_in[7];
    float* out = (float*)d_out;

    fused_kernel<<<GRID, 256>>>(Z, su, cp, ts, snd, rcv, nds);
    final_kernel<<<1, 512>>>(beta, out);
}